// round 13
// baseline (speedup 1.0000x reference)
#include <cuda_runtime.h>
#include <cstdint>

#define SLEN   53
#define NPIX   (SLEN * SLEN)     // 2809
#define TPB    256
#define NUNITS (SLEN * 14)       // 742 strip units; strip 13 = row 52 only

// Gaussian sentinel table: covers idx in [-225, 276]
#define TBIAS  225
#define TSIZE  502

// atan lookup table: node i -> x = (i-1024)*0.01, covers [-10.24, 10.23]
#define ASIZE  2048
#define ADELTA 0.01f

__device__ __forceinline__ float frcp_(float x){ float r; asm("rcp.approx.ftz.f32 %0, %1;" : "=f"(r) : "f"(x)); return r; }
__device__ __forceinline__ float flg2_(float x){ float r; asm("lg2.approx.ftz.f32 %0, %1;" : "=f"(r) : "f"(x)); return r; }
__device__ __forceinline__ float frsq_(float x){ float r; asm("rsqrt.approx.ftz.f32 %0, %1;" : "=f"(r) : "f"(x)); return r; }

// smem scalar slots
#define S_Q     0
#define S_INVQ  1
#define S_QF    2
#define S_QF100 3   // qfact * 100 (index-space scaling for atan table)
#define S_BCA   4   // bsafe * cosp
#define S_BSA   5   // bsafe * sinp
#define S_BCL   6   // bsafe * cosp * 0.5*ln2
#define S_BSL   7   // bsafe * sinp * 0.5*ln2
#define S_K1    8   // cx26*cosp + cy26*sinp
#define S_K2    9   // cy26*cosp - cx26*sinp
#define S_COSP  10
#define S_SINP  11

__global__ void __launch_bounds__(TPB, 8)
lens_decoder_kernel(const float* __restrict__ params,   // [ntiles, 12]
                    const float* __restrict__ bools,    // [ntiles]
                    float* __restrict__ out)            // [ntiles, NPIX]
{
    __shared__ float  sc[12];
    __shared__ float2 etab[TSIZE];
    __shared__ float2 atab[ASIZE];      // (atan(x_i), atan(x_{i+1})-atan(x_i))

    const int tid  = threadIdx.x;
    const int tile = blockIdx.x;
    float* o = out + (size_t)tile * NPIX;

    // ---- zero-tile fast path (~30%): vectorized exact-0 fill ----
    if (bools[tile] == 0.0f) {
        const int phase = (int)(((unsigned long long)o >> 2) & 3ull);
        const int head  = (4 - phase) & 3;
        if (tid < head) o[tid] = 0.0f;
        float4* ov = (float4*)(o + head);
        const int nvec = (NPIX - head) >> 2;
        for (int p = tid; p < nvec; p += TPB)
            ov[p] = make_float4(0.0f, 0.0f, 0.0f, 0.0f);
        const int done = head + (nvec << 2);
        if (done + tid < NPIX) o[done + tid] = 0.0f;
        return;
    }

    // ---- parallel preamble (single sync); disjoint writers ----

    // atan table: 8 consecutive nodes per thread, one atanf + midpoint steps.
    // delta_i = ADELTA / (1 + m_i^2), m_i = x_i + ADELTA/2 (O(D^3) accurate).
    {
        const int i0 = tid * 8;
        const float x0 = (float)(i0 - 1024) * ADELTA;
        float v = atanf(x0);
        #pragma unroll
        for (int c = 0; c < 8; c++) {
            const float m = x0 + ((float)c * ADELTA + 0.5f * ADELTA);
            const float g = ADELTA * frcp_(fmaf(m, m, 1.0f));
            atab[i0 + c] = make_float2(v, g);
            v += g;
        }
    }

    // Gaussian table margins: entries [0,224] (idx<0) and [278,501] (idx>52)
    if (tid < TBIAS)       etab[tid]       = make_float2(0.0f, 0.0f);
    if (tid < 224)         etab[278 + tid] = make_float2(0.0f, 0.0f);
    // real entries: idx k in [0,52] -> entry 225+k; k=52 is the zero edge row
    if (tid <= 52) {
        if (tid == 52) {
            etab[TBIAS + 52] = make_float2(0.0f, 0.0f);
        } else {
            const float* pr = params + tile * 12;
            const float flux  = fmaf(pr[0], 1000.0f, 100.0f);
            const float sigma = fmaf(pr[3], 3.0f, 1.0f);
            const float s2    = sigma * sigma;
            const float sAm   = sqrtf(flux / (6.283185307179586f * s2));
            const float n2s2  = -0.5f / s2;
            const float d0 = (float)tid - 26.0f;
            const float d1 = (float)(tid + 1) - 26.0f;
            const float e0 = sAm * expf(n2s2 * d0 * d0);
            const float e1 = sAm * expf(n2s2 * d1 * d1);
            etab[TBIAS + tid] = make_float2(e0, e1 - e0);
        }
    }
    // lens scalars
    if (tid == 64) {
        const float* pr = params + tile * 12;
        const float b   = pr[7];
        const float cx26 = pr[8] + 26.0f;
        const float cy26 = pr[9] + 26.0f;
        const float e1p = pr[10];
        const float e2p = pr[11];
        const float ell = sqrtf(e1p * e1p + e2p * e2p);
        const float q   = (1.0f - ell) / (1.0f + ell);
        const float phir = atanf(e2p / e1p);
        float sinp, cosp;
        sincosf(phir, &sinp, &cosp);
        const float invq  = 1.0f / q;
        // data guarantees q in [0.1,0.9] -> qfact >= 0.459 >> eps (fallback dead)
        const float qfact = sqrtf(invq - q);
        const float bsafe = b / qfact;
        const float bcA = bsafe * cosp;
        const float bsA = bsafe * sinp;
        sc[S_Q]     = q;
        sc[S_INVQ]  = invq;
        sc[S_QF]    = qfact;
        sc[S_QF100] = qfact * 100.0f;        // 1/ADELTA = 100
        sc[S_BCA]   = bcA;
        sc[S_BSA]   = bsA;
        sc[S_BCL]   = bcA * 0.34657359028f;  // * 0.5*ln2
        sc[S_BSL]   = bsA * 0.34657359028f;
        sc[S_K1]    = fmaf(cx26, cosp,  cy26 * sinp);
        sc[S_K2]    = fmaf(cy26, cosp, -cx26 * sinp);
        sc[S_COSP]  = cosp;
        sc[S_SINP]  = sinp;
    }
    __syncthreads();

    const float q     = sc[S_Q];
    const float invq  = sc[S_INVQ];
    const float qfact = sc[S_QF];
    const float qf100 = sc[S_QF100];
    const float bcA   = sc[S_BCA];
    const float bsA   = sc[S_BSA];
    const float bcL   = sc[S_BCL];
    const float bsL   = sc[S_BSL];
    const float K1    = sc[S_K1];
    const float K2    = sc[S_K2];
    const float cosp  = sc[S_COSP];
    const float sinp  = sc[S_SINP];

    const float scale = 53.0f / 52.0f;
    const float dxs_y = scale * sinp;
    const float dys_y = scale * cosp;
    const float2* etp = &etab[TBIAS];      // bias folded into base

    // per-pixel body
    auto pixel = [&](float xsie, float ysie, float xc, float yc) -> float {
        const float t = fmaf(q * xsie, xsie, fmaf(invq * ysie, ysie, 1e-12f));
        const float r = frsq_(t);
        // atan via table: s = zx*100 + 1024, zx = qfact*xsie*r in [-9.95, 9.95]
        const float s  = fmaf(xsie * r, qf100, 1024.0f);     // [29, 2019]
        const float zy = (ysie * r) * qfact;                 // |zy| <= 0.995

        const int ai = __float2int_rd(s);
        const float af = s - (float)ai;
        const float2 at = atab[ai];
        const float A = fmaf(af, at.y, at.x);

        const float L = flg2_(1.0f + zy) - flg2_(1.0f - zy);   // atanh/(0.5 ln2)

        const float xs = fmaf(-bcA, A, fmaf( bsL, L, xc));
        const float ys = fmaf(-bsA, A, fmaf(-bcL, L, yc));

        const int ix = __float2int_rd(xs);        // floor, in [-222, 274]
        const int iy = __float2int_rd(ys);
        const float ffx = xs - (float)ix;
        const float ffy = ys - (float)iy;

        const float2 exd = etp[ix];
        const float2 eyd = etp[iy];
        const float wx = fmaf(ffx, exd.y, exd.x);
        const float wy = fmaf(ffy, eyd.y, eyd.x);
        return wx * wy;
    };

    // ---- main: 742 strip units; strips 0..12 full 4 rows, strip 13 = row 52 ----
    for (int u = tid; u < NUNITS; u += TPB) {
        const int strip = (u * 1237) >> 16;        // == u/53 for u < 742
        const int j     = u - strip * 53;
        const bool full = strip < 13;              // one bounds check per unit

        const float xc  = fmaf((float)j,     scale,        -1.0f); // x + 26
        const float yc0 = fmaf((float)strip, 4.0f * scale, -1.0f); // y + 26

        float xsie = fmaf(yc0, sinp, fmaf(xc, cosp, -K1));
        float ysie = fmaf(yc0, cosp, -fmaf(xc, sinp, K2));
        float yc   = yc0;

        float* ocol = o + strip * (4 * SLEN) + j;

        ocol[0] = pixel(xsie, ysie, xc, yc);
        #pragma unroll
        for (int k = 1; k < 4; k++) {
            xsie += dxs_y;
            ysie += dys_y;
            yc   += scale;
            if (full)
                ocol[k * SLEN] = pixel(xsie, ysie, xc, yc);
        }
    }
}

extern "C" void kernel_launch(void* const* d_in, const int* in_sizes, int n_in,
                              void* d_out, int out_size)
{
    const float* params = (const float*)d_in[0];   // lens_params  [4096,1,12]
    const float* bmask  = (const float*)d_in[1];   // bools        [4096,1,1]
    float* out = (float*)d_out;

    const int ntiles = out_size / NPIX;            // 4096
    lens_decoder_kernel<<<ntiles, TPB>>>(params, bmask, out);
}

// round 14
// speedup vs baseline: 1.1209x; 1.1209x over previous
#include <cuda_runtime.h>
#include <cstdint>

#define SLEN   53
#define NPIX   (SLEN * SLEN)     // 2809
#define TPB    256
#define NUNITS (SLEN * 14)       // 742 strip units; strip 13 = row 52 only

// Gaussian sentinel table: covers idx in [-225, 276]
#define TBIAS  225
#define TSIZE  502

// atan lookup table: node i -> x = (i-512)*0.02, covers [-10.24, 10.22]
#define ASIZE  1024
#define ADELTA 0.02f

__device__ __forceinline__ float frcp_(float x){ float r; asm("rcp.approx.ftz.f32 %0, %1;" : "=f"(r) : "f"(x)); return r; }
__device__ __forceinline__ float flg2_(float x){ float r; asm("lg2.approx.ftz.f32 %0, %1;" : "=f"(r) : "f"(x)); return r; }
__device__ __forceinline__ float frsq_(float x){ float r; asm("rsqrt.approx.ftz.f32 %0, %1;" : "=f"(r) : "f"(x)); return r; }

// Cephes-style atan (seed for the table build only). Max err ~3e-7.
__device__ __forceinline__ float fast_atan(float v) {
    float a  = fabsf(v);
    bool  c1 = a > 2.414213562f;
    bool  c2 = a > 0.414213562f;
    float num = c1 ? -1.0f : (a - 1.0f);
    float den = c1 ?  a    : (a + 1.0f);
    float xr  = num * frcp_(den);
    float x   = c2 ? xr : a;
    float y0  = c1 ? 1.57079632679f : (c2 ? 0.78539816339f : 0.0f);
    float z = x * x;
    float p = fmaf(8.05374449538e-2f, z, -1.38776856032e-1f);
    p = fmaf(p, z, 1.99777106478e-1f);
    p = fmaf(p, z, -3.33329491539e-1f);
    float y = fmaf(p * z, x, x) + y0;
    return copysignf(y, v);
}

// smem scalar slots
#define S_Q     0
#define S_INVQ  1
#define S_QF    2
#define S_QF50  3   // qfact * 50 (index-space scaling for atan table)
#define S_BCA   4   // bsafe * cosp
#define S_BSA   5   // bsafe * sinp
#define S_BCL   6   // bsafe * cosp * 0.5*ln2
#define S_BSL   7   // bsafe * sinp * 0.5*ln2
#define S_K1    8   // cx26*cosp + cy26*sinp
#define S_K2    9   // cy26*cosp - cx26*sinp
#define S_COSP  10
#define S_SINP  11

__global__ void __launch_bounds__(TPB)
lens_decoder_kernel(const float* __restrict__ params,   // [ntiles, 12]
                    const float* __restrict__ bools,    // [ntiles]
                    float* __restrict__ out)            // [ntiles, NPIX]
{
    __shared__ float  sc[12];
    __shared__ float2 etab[TSIZE];
    __shared__ float2 atab[ASIZE];      // (sag-corrected atan(x_i), midpoint slope)

    const int tid  = threadIdx.x;
    const int tile = blockIdx.x;
    float* o = out + (size_t)tile * NPIX;

    // ---- zero-tile fast path (~30%): vectorized exact-0 fill ----
    if (bools[tile] == 0.0f) {
        const int phase = (int)(((unsigned long long)o >> 2) & 3ull);
        const int head  = (4 - phase) & 3;
        if (tid < head) o[tid] = 0.0f;
        float4* ov = (float4*)(o + head);
        const int nvec = (NPIX - head) >> 2;
        for (int p = tid; p < nvec; p += TPB)
            ov[p] = make_float4(0.0f, 0.0f, 0.0f, 0.0f);
        const int done = head + (nvec << 2);
        if (done + tid < NPIX) o[done + tid] = 0.0f;
        return;
    }

    // ---- parallel preamble (single sync); disjoint writers ----

    // atan table: 4 consecutive nodes per thread.
    // Seed with inline Cephes atan (cheap), then midpoint-rule increments
    // g_i = D/(1+m_i^2). Stored value is sag-compensated: v + m*g^2/4
    // (half the linear-interp sag -> equioscillating error ~D^2/16*|f''|).
    {
        const int i0 = tid * 4;
        const float x0 = (float)(i0 - 512) * ADELTA;
        float v = fast_atan(x0);
        #pragma unroll
        for (int c = 0; c < 4; c++) {
            const float m = x0 + ((float)c * ADELTA + 0.5f * ADELTA);
            const float g = ADELTA * frcp_(fmaf(m, m, 1.0f));
            atab[i0 + c] = make_float2(fmaf(0.25f * m, g * g, v), g);
            v += g;
        }
    }

    // Gaussian table margins: entries [0,224] (idx<0) and [278,501] (idx>52)
    if (tid < TBIAS)       etab[tid]       = make_float2(0.0f, 0.0f);
    if (tid < 224)         etab[278 + tid] = make_float2(0.0f, 0.0f);
    // real entries: idx k in [0,52] -> entry 225+k; k=52 is the zero edge row
    if (tid <= 52) {
        if (tid == 52) {
            etab[TBIAS + 52] = make_float2(0.0f, 0.0f);
        } else {
            const float* pr = params + tile * 12;
            const float flux  = fmaf(pr[0], 1000.0f, 100.0f);
            const float sigma = fmaf(pr[3], 3.0f, 1.0f);
            const float s2    = sigma * sigma;
            const float sAm   = sqrtf(flux / (6.283185307179586f * s2));
            const float n2s2  = -0.5f / s2;
            const float d0 = (float)tid - 26.0f;
            const float d1 = (float)(tid + 1) - 26.0f;
            const float e0 = sAm * expf(n2s2 * d0 * d0);
            const float e1 = sAm * expf(n2s2 * d1 * d1);
            etab[TBIAS + tid] = make_float2(e0, e1 - e0);
        }
    }
    // lens scalars
    if (tid == 64) {
        const float* pr = params + tile * 12;
        const float b   = pr[7];
        const float cx26 = pr[8] + 26.0f;
        const float cy26 = pr[9] + 26.0f;
        const float e1p = pr[10];
        const float e2p = pr[11];
        const float ell = sqrtf(e1p * e1p + e2p * e2p);
        const float q   = (1.0f - ell) / (1.0f + ell);
        const float phir = atanf(e2p / e1p);
        float sinp, cosp;
        sincosf(phir, &sinp, &cosp);
        const float invq  = 1.0f / q;
        // data guarantees q in [0.1,0.9] -> qfact >= 0.459 >> eps (fallback dead)
        const float qfact = sqrtf(invq - q);
        const float bsafe = b / qfact;
        const float bcA = bsafe * cosp;
        const float bsA = bsafe * sinp;
        sc[S_Q]    = q;
        sc[S_INVQ] = invq;
        sc[S_QF]   = qfact;
        sc[S_QF50] = qfact * 50.0f;          // 1/ADELTA = 50
        sc[S_BCA]  = bcA;
        sc[S_BSA]  = bsA;
        sc[S_BCL]  = bcA * 0.34657359028f;   // * 0.5*ln2
        sc[S_BSL]  = bsA * 0.34657359028f;
        sc[S_K1]   = fmaf(cx26, cosp,  cy26 * sinp);
        sc[S_K2]   = fmaf(cy26, cosp, -cx26 * sinp);
        sc[S_COSP] = cosp;
        sc[S_SINP] = sinp;
    }
    __syncthreads();

    const float q     = sc[S_Q];
    const float invq  = sc[S_INVQ];
    const float qfact = sc[S_QF];
    const float qf50  = sc[S_QF50];
    const float bcA   = sc[S_BCA];
    const float bsA   = sc[S_BSA];
    const float bcL   = sc[S_BCL];
    const float bsL   = sc[S_BSL];
    const float K1    = sc[S_K1];
    const float K2    = sc[S_K2];
    const float cosp  = sc[S_COSP];
    const float sinp  = sc[S_SINP];

    const float scale = 53.0f / 52.0f;
    const float dxs_y = scale * sinp;
    const float dys_y = scale * cosp;
    const float2* etp = &etab[TBIAS];      // bias folded into base

    // per-pixel body
    auto pixel = [&](float xsie, float ysie, float xc, float yc) -> float {
        const float t = fmaf(q * xsie, xsie, fmaf(invq * ysie, ysie, 1e-12f));
        const float r = frsq_(t);
        // atan via table: s = zx*50 + 512, zx = qfact*xsie*r in [-9.95, 9.95]
        const float s  = fmaf(xsie * r, qf50, 512.0f);      // [14.5, 1009.5]
        const float zy = (ysie * r) * qfact;                // |zy| <= 0.995

        const int ai = __float2int_rd(s);
        const float af = s - (float)ai;
        const float2 at = atab[ai];
        const float A = fmaf(af, at.y, at.x);

        const float L = flg2_(1.0f + zy) - flg2_(1.0f - zy);   // atanh/(0.5 ln2)

        const float xs = fmaf(-bcA, A, fmaf( bsL, L, xc));
        const float ys = fmaf(-bsA, A, fmaf(-bcL, L, yc));

        const int ix = __float2int_rd(xs);        // floor, in [-222, 274]
        const int iy = __float2int_rd(ys);
        const float ffx = xs - (float)ix;
        const float ffy = ys - (float)iy;

        const float2 exd = etp[ix];
        const float2 eyd = etp[iy];
        const float wx = fmaf(ffx, exd.y, exd.x);
        const float wy = fmaf(ffy, eyd.y, eyd.x);
        return wx * wy;
    };

    // ---- main: 742 strip units; strips 0..12 full 4 rows, strip 13 = row 52 ----
    for (int u = tid; u < NUNITS; u += TPB) {
        const int strip = (u * 1237) >> 16;        // == u/53 for u < 742
        const int j     = u - strip * 53;
        const bool full = strip < 13;              // one bounds check per unit

        const float xc  = fmaf((float)j,     scale,        -1.0f); // x + 26
        const float yc0 = fmaf((float)strip, 4.0f * scale, -1.0f); // y + 26

        float xsie = fmaf(yc0, sinp, fmaf(xc, cosp, -K1));
        float ysie = fmaf(yc0, cosp, -fmaf(xc, sinp, K2));
        float yc   = yc0;

        float* ocol = o + strip * (4 * SLEN) + j;

        ocol[0] = pixel(xsie, ysie, xc, yc);
        #pragma unroll
        for (int k = 1; k < 4; k++) {
            xsie += dxs_y;
            ysie += dys_y;
            yc   += scale;
            if (full)
                ocol[k * SLEN] = pixel(xsie, ysie, xc, yc);
        }
    }
}

extern "C" void kernel_launch(void* const* d_in, const int* in_sizes, int n_in,
                              void* d_out, int out_size)
{
    const float* params = (const float*)d_in[0];   // lens_params  [4096,1,12]
    const float* bmask  = (const float*)d_in[1];   // bools        [4096,1,1]
    float* out = (float*)d_out;

    const int ntiles = out_size / NPIX;            // 4096
    lens_decoder_kernel<<<ntiles, TPB>>>(params, bmask, out);
}

// round 15
// speedup vs baseline: 1.1574x; 1.0326x over previous
#include <cuda_runtime.h>
#include <cstdint>

#define SLEN   53
#define NPIX   (SLEN * SLEN)     // 2809
#define TPB    256
#define NUNITS (SLEN * 14)       // 742 strip units; strip 13 = row 52 only

// Gaussian sentinel table: covers idx in [-225, 276]
#define TBIAS  225
#define TSIZE  502

// atan lookup table: node i -> x = (i-512)*0.02, covers [-10.24, 10.22]
#define ASIZE  1024
#define ADELTA 0.02f

__device__ __forceinline__ float frcp_(float x){ float r; asm("rcp.approx.ftz.f32 %0, %1;" : "=f"(r) : "f"(x)); return r; }
__device__ __forceinline__ float flg2_(float x){ float r; asm("lg2.approx.ftz.f32 %0, %1;" : "=f"(r) : "f"(x)); return r; }
__device__ __forceinline__ float frsq_(float x){ float r; asm("rsqrt.approx.ftz.f32 %0, %1;" : "=f"(r) : "f"(x)); return r; }

// Cephes-style atan (seed for the table build only). Max err ~3e-7.
__device__ __forceinline__ float fast_atan(float v) {
    float a  = fabsf(v);
    bool  c1 = a > 2.414213562f;
    bool  c2 = a > 0.414213562f;
    float num = c1 ? -1.0f : (a - 1.0f);
    float den = c1 ?  a    : (a + 1.0f);
    float xr  = num * frcp_(den);
    float x   = c2 ? xr : a;
    float y0  = c1 ? 1.57079632679f : (c2 ? 0.78539816339f : 0.0f);
    float z = x * x;
    float p = fmaf(8.05374449538e-2f, z, -1.38776856032e-1f);
    p = fmaf(p, z, 1.99777106478e-1f);
    p = fmaf(p, z, -3.33329491539e-1f);
    float y = fmaf(p * z, x, x) + y0;
    return copysignf(y, v);
}

// smem scalar slots (scaled-frame constants)
#define S_CXP  0   // sq*cosp     (x' rotation)
#define S_SXP  1   // sq*sinp
#define S_K1X  2   // sq*K1
#define S_CYP  3   // siq*cosp    (y' rotation)
#define S_SYP  4   // siq*sinp
#define S_K2Y  5   // siq*K2
#define S_CS50 6   // 50*qfact/sq (atan table index scale)
#define S_CZY  7   // qfact*sq    (zy scale)
#define S_BCA  8   // bsafe*cosp
#define S_BSA  9   // bsafe*sinp
#define S_BCL  10  // bsafe*cosp*0.5*ln2
#define S_BSL  11  // bsafe*sinp*0.5*ln2

__global__ void __launch_bounds__(TPB, 7)
lens_decoder_kernel(const float* __restrict__ params,   // [ntiles, 12]
                    const float* __restrict__ bools,    // [ntiles]
                    float* __restrict__ out)            // [ntiles, NPIX]
{
    __shared__ float  sc[12];
    __shared__ float2 etab[TSIZE];
    __shared__ float2 atab[ASIZE];      // (sag-corrected atan(x_i), midpoint slope)

    const int tid  = threadIdx.x;
    const int tile = blockIdx.x;
    float* o = out + (size_t)tile * NPIX;

    // ---- zero-tile fast path (~30%): vectorized exact-0 fill ----
    if (bools[tile] == 0.0f) {
        const int phase = (int)(((unsigned long long)o >> 2) & 3ull);
        const int head  = (4 - phase) & 3;
        if (tid < head) o[tid] = 0.0f;
        float4* ov = (float4*)(o + head);
        const int nvec = (NPIX - head) >> 2;
        for (int p = tid; p < nvec; p += TPB)
            ov[p] = make_float4(0.0f, 0.0f, 0.0f, 0.0f);
        const int done = head + (nvec << 2);
        if (done + tid < NPIX) o[done + tid] = 0.0f;
        return;
    }

    // ---- parallel preamble (single sync); disjoint writers ----

    // atan table: 4 consecutive nodes per thread, Cephes seed + midpoint
    // increments g_i = D/(1+m_i^2); stored values sag-compensated.
    {
        const int i0 = tid * 4;
        const float x0 = (float)(i0 - 512) * ADELTA;
        float v = fast_atan(x0);
        #pragma unroll
        for (int c = 0; c < 4; c++) {
            const float m = x0 + ((float)c * ADELTA + 0.5f * ADELTA);
            const float g = ADELTA * frcp_(fmaf(m, m, 1.0f));
            atab[i0 + c] = make_float2(fmaf(0.25f * m, g * g, v), g);
            v += g;
        }
    }

    // Gaussian table margins: entries [0,224] (idx<0) and [278,501] (idx>52)
    if (tid < TBIAS)       etab[tid]       = make_float2(0.0f, 0.0f);
    if (tid < 224)         etab[278 + tid] = make_float2(0.0f, 0.0f);
    // real entries: idx k in [0,52] -> entry 225+k; k=52 is the zero edge row
    if (tid <= 52) {
        if (tid == 52) {
            etab[TBIAS + 52] = make_float2(0.0f, 0.0f);
        } else {
            const float* pr = params + tile * 12;
            const float flux  = fmaf(pr[0], 1000.0f, 100.0f);
            const float sigma = fmaf(pr[3], 3.0f, 1.0f);
            const float s2    = sigma * sigma;
            const float sAm   = sqrtf(flux / (6.283185307179586f * s2));
            const float n2s2  = -0.5f / s2;
            const float d0 = (float)tid - 26.0f;
            const float d1 = (float)(tid + 1) - 26.0f;
            const float e0 = sAm * expf(n2s2 * d0 * d0);
            const float e1 = sAm * expf(n2s2 * d1 * d1);
            etab[TBIAS + tid] = make_float2(e0, e1 - e0);
        }
    }
    // lens scalars
    if (tid == 64) {
        const float* pr = params + tile * 12;
        const float b   = pr[7];
        const float cx26 = pr[8] + 26.0f;
        const float cy26 = pr[9] + 26.0f;
        const float e1p = pr[10];
        const float e2p = pr[11];
        const float ell = sqrtf(e1p * e1p + e2p * e2p);
        const float q   = (1.0f - ell) / (1.0f + ell);
        const float phir = atanf(e2p / e1p);
        float sinp, cosp;
        sincosf(phir, &sinp, &cosp);
        const float invq  = 1.0f / q;
        // data guarantees q in [0.1,0.9] -> qfact >= 0.459 >> eps (fallback dead)
        const float qfact = sqrtf(invq - q);
        const float bsafe = b / qfact;
        const float sq  = sqrtf(q);
        const float siq = sqrtf(invq);
        const float K1 = fmaf(cx26, cosp,  cy26 * sinp);
        const float K2 = fmaf(cy26, cosp, -cx26 * sinp);
        const float bcA = bsafe * cosp;
        const float bsA = bsafe * sinp;
        sc[S_CXP]  = sq * cosp;
        sc[S_SXP]  = sq * sinp;
        sc[S_K1X]  = sq * K1;
        sc[S_CYP]  = siq * cosp;
        sc[S_SYP]  = siq * sinp;
        sc[S_K2Y]  = siq * K2;
        sc[S_CS50] = qfact * 50.0f * siq;    // 50*qfact/sq (siq = 1/sq)
        sc[S_CZY]  = qfact * sq;
        sc[S_BCA]  = bcA;
        sc[S_BSA]  = bsA;
        sc[S_BCL]  = bcA * 0.34657359028f;   // * 0.5*ln2
        sc[S_BSL]  = bsA * 0.34657359028f;
    }
    __syncthreads();

    const float cxp  = sc[S_CXP];
    const float sxp  = sc[S_SXP];
    const float K1x  = sc[S_K1X];
    const float cyp  = sc[S_CYP];
    const float syp  = sc[S_SYP];
    const float K2y  = sc[S_K2Y];
    const float cs50 = sc[S_CS50];
    const float czy  = sc[S_CZY];
    const float bcA  = sc[S_BCA];
    const float bsA  = sc[S_BSA];
    const float bcL  = sc[S_BCL];
    const float bsL  = sc[S_BSL];

    const float scale = 53.0f / 52.0f;
    const float dxp_y = scale * sxp;       // d(x')/d(row)
    const float dyp_y = scale * cyp;       // d(y')/d(row)
    const float2* etp = &etab[TBIAS];      // bias folded into base

    // per-pixel body: scaled-frame coords (x' = sq*xsie, y' = siq*ysie)
    auto pixel = [&](float xp, float yp, float xc, float yc) -> float {
        const float t = fmaf(xp, xp, fmaf(yp, yp, 1e-12f));
        const float r = frsq_(t);
        const float s  = fmaf(xp * r, cs50, 512.0f);   // atan index, [14.5,1009.5]
        const float zy = (yp * r) * czy;               // |zy| <= 0.995

        const int ai = __float2int_rd(s);
        const float af = s - (float)ai;
        const float2 at = atab[ai];
        const float A = fmaf(af, at.y, at.x);

        const float L = flg2_(1.0f + zy) - flg2_(1.0f - zy);   // atanh/(0.5 ln2)

        const float xs = fmaf(-bcA, A, fmaf( bsL, L, xc));
        const float ys = fmaf(-bsA, A, fmaf(-bcL, L, yc));

        const int ix = __float2int_rd(xs);        // floor, in [-222, 274]
        const int iy = __float2int_rd(ys);
        const float ffx = xs - (float)ix;
        const float ffy = ys - (float)iy;

        const float2 exd = etp[ix];
        const float2 eyd = etp[iy];
        const float wx = fmaf(ffx, exd.y, exd.x);
        const float wy = fmaf(ffy, eyd.y, eyd.x);
        return wx * wy;
    };

    // ---- main: 742 strip units; strips 0..12 full 4 rows, strip 13 = row 52 ----
    for (int u = tid; u < NUNITS; u += TPB) {
        const int strip = (u * 1237) >> 16;        // == u/53 for u < 742
        const int j     = u - strip * 53;
        const bool full = strip < 13;              // one bounds check per unit

        const float xc  = fmaf((float)j,     scale,        -1.0f); // x + 26
        const float yc0 = fmaf((float)strip, 4.0f * scale, -1.0f); // y + 26

        float xp = fmaf(yc0, sxp, fmaf(xc, cxp, -K1x));
        float yp = fmaf(yc0, cyp, -fmaf(xc, syp, K2y));
        float yc = yc0;

        float* ocol = o + strip * (4 * SLEN) + j;

        ocol[0] = pixel(xp, yp, xc, yc);
        #pragma unroll
        for (int k = 1; k < 4; k++) {
            xp += dxp_y;
            yp += dyp_y;
            yc += scale;
            if (full)
                ocol[k * SLEN] = pixel(xp, yp, xc, yc);
        }
    }
}

extern "C" void kernel_launch(void* const* d_in, const int* in_sizes, int n_in,
                              void* d_out, int out_size)
{
    const float* params = (const float*)d_in[0];   // lens_params  [4096,1,12]
    const float* bmask  = (const float*)d_in[1];   // bools        [4096,1,1]
    float* out = (float*)d_out;

    const int ntiles = out_size / NPIX;            // 4096
    lens_decoder_kernel<<<ntiles, TPB>>>(params, bmask, out);
}